// round 1
// baseline (speedup 1.0000x reference)
#include <cuda_runtime.h>
#include <math.h>

#define BB 8
#define TT 96
#define NN 20000
#define PP 12
#define LL 3
#define DD 32
#define CC 128
#define MM 64

// ---------------- scratch (static device globals; no dynamic allocation) ----
__device__ float    g_h   [BB*NN*CC];
__device__ float    g_skip[BB*NN*CC];
__device__ float    g_u   [BB*NN*CC];
__device__ float    g_phiq[BB*NN*MM];
__device__ float    g_phik[BB*NN*MM];
__device__ float    g_den [BB*NN];
__device__ float    g_kv  [BB*MM*CC];
__device__ float    g_ksum[BB*MM];
__device__ unsigned g_stab[BB];
__device__ float    g_cb  [BB*DD];
__device__ float    g_bp1 [BB*DD];
__device__ float    g_bp2 [BB*DD];
__device__ int      g_tod [BB];
__device__ int      g_dow [BB];
__device__ float    g_wcomb[LL*CC*2*CC];   // [layer][k(128)][j(256)]; j<128 gate, j>=128 value

#define ALPHA 0.84089641525371454f   // 2 * 32^(-1/4)  (inv_sqrt_tau * d^-0.25)
#define RATIO 0.125f                 // 1/sqrt(64)
#define RFEPS 1e-6f

__device__ __forceinline__ unsigned fenc(float f) {
    unsigned b = __float_as_uint(f);
    return (b & 0x80000000u) ? ~b : (b | 0x80000000u);
}
__device__ __forceinline__ float fdec(unsigned u) {
    return (u & 0x80000000u) ? __uint_as_float(u ^ 0x80000000u) : __uint_as_float(~u);
}

// ---------------- K0: per-batch constants --------------------------------
__global__ void k_prep(const float* __restrict__ xm, const float* __restrict__ input_w,
                       const float* __restrict__ input_b,
                       const float* __restrict__ time_tab, const float* __restrict__ week_tab,
                       const float* __restrict__ w1w, const float* __restrict__ w1b,
                       const float* __restrict__ w2w, const float* __restrict__ w2b) {
    int tid = threadIdx.x;
    if (tid < BB) {
        float m0 = xm[(tid*TT + TT-1)*2 + 0];
        float m1 = xm[(tid*TT + TT-1)*2 + 1];
        int t = (int)(m0 * (float)TT); t = min(max(t, 0), TT-1);
        int w = (int)(m1 * 7.0f);      w = min(max(w, 0), 6);
        g_tod[tid] = t; g_dow[tid] = w; g_stab[tid] = 0u;
    }
    for (int i = tid; i < BB*MM; i += blockDim.x) g_ksum[i] = 0.f;
    __syncthreads();
    int b = tid >> 5, c = tid & 31;
    // input-embedding constant from x_mark broadcast features
    float cb = input_b[c];
    for (int t = 0; t < TT; t++) {
        cb += xm[(b*TT + t)*2 + 0] * input_w[c*288 + 96  + t];
        cb += xm[(b*TT + t)*2 + 1] * input_w[c*288 + 192 + t];
    }
    g_cb[b*DD + c] = cb;
    int tod = g_tod[b], dow = g_dow[b];
    float b1 = w1b[c], b2 = w2b[c];
    for (int d = 0; d < DD; d++) {
        float te = time_tab[tod*DD + d], we = week_tab[dow*DD + d];
        b1 += te * w1w[c*96 + 32 + d] + we * w1w[c*96 + 64 + d];
        b2 += te * w2w[c*96 + 32 + d] + we * w2w[c*96 + 64 + d];
    }
    g_bp1[b*DD + c] = b1;
    g_bp2[b*DD + c] = b2;
}

// ---------------- K0b: combined transposed layer weights -----------------
__global__ void k_wcomb(const float* __restrict__ in_w, const float* __restrict__ out_w) {
    int idx = blockIdx.x*256 + threadIdx.x;          // < 3*128*256 = 98304
    int i = idx / (CC*256);
    int r = idx % (CC*256);
    int k = r >> 8;
    int j = r & 255;
    g_wcomb[idx] = (j < CC) ? in_w[(i*CC + j)*CC + k]
                            : out_w[(i*CC + (j-CC))*CC + k];
}

// ---------------- K1: input embedding + build h / skip -------------------
__global__ void k_embed(const float* __restrict__ x, const float* __restrict__ input_w,
                        const float* __restrict__ node_emb,
                        const float* __restrict__ time_tab, const float* __restrict__ week_tab) {
    __shared__ float wT[TT*DD];   // wT[t*32+c] = input_w[c][t]
    __shared__ float scb[DD];
    int tid = threadIdx.x, b = blockIdx.y;
    for (int i = tid; i < TT*DD; i += 256) {
        int t = i >> 5, c = i & 31;
        wT[i] = input_w[c*288 + t];
    }
    if (tid < DD) scb[tid] = g_cb[b*DD + tid];
    __syncthreads();
    int n = blockIdx.x*256 + tid;
    if (n >= NN) return;
    float acc[DD];
#pragma unroll
    for (int c = 0; c < DD; c++) acc[c] = scb[c];
    for (int t = 0; t < TT; t++) {
        float xv = x[(b*TT + t)*NN + n];
#pragma unroll
        for (int c = 0; c < DD; c++) acc[c] += xv * wT[t*DD + c];
    }
    int base = (b*NN + n)*CC;
    int tod = g_tod[b], dow = g_dow[b];
#pragma unroll
    for (int q = 0; q < 8; q++) {
        float4 v = make_float4(acc[q*4], acc[q*4+1], acc[q*4+2], acc[q*4+3]);
        *(float4*)&g_h[base + q*4] = v;  *(float4*)&g_skip[base + q*4] = v;
    }
#pragma unroll
    for (int q = 0; q < 8; q++) {
        float4 v = *(const float4*)&node_emb[n*DD + q*4];
        *(float4*)&g_h[base + 32 + q*4] = v;  *(float4*)&g_skip[base + 32 + q*4] = v;
    }
#pragma unroll
    for (int q = 0; q < 8; q++) {
        float4 v = *(const float4*)&time_tab[tod*DD + q*4];
        *(float4*)&g_h[base + 64 + q*4] = v;  *(float4*)&g_skip[base + 64 + q*4] = v;
    }
#pragma unroll
    for (int q = 0; q < 8; q++) {
        float4 v = *(const float4*)&week_tab[dow*DD + q*4];
        *(float4*)&g_h[base + 96 + q*4] = v;  *(float4*)&g_skip[base + 96 + q*4] = v;
    }
}

// ---------------- K2: random-feature maps --------------------------------
// 256 threads: 4 rows/block. phi_q fully; phi_k raw (dash-diag) + global dash max
__global__ void k_phi(const float* __restrict__ node_emb,
                      const float* __restrict__ w1w, const float* __restrict__ w2w,
                      const float* __restrict__ proj) {
    __shared__ float w1t[DD*DD], w2t[DD*DD];   // [d][c]
    __shared__ float pT[DD*MM];                // [d][m]
    __shared__ float snode[4*DD];
    __shared__ float sd1[4*DD], sd2[4*DD];
    __shared__ float sdiag1[4], sdiag2[4];
    __shared__ float swm[8], swm2[8];
    int tid = threadIdx.x, b = blockIdx.y;
    int base = blockIdx.x*4;
    for (int i = tid; i < DD*DD; i += 256) {
        int c = i >> 5, d = i & 31;
        w1t[d*DD + c] = w1w[c*96 + d];
        w2t[d*DD + c] = w2w[c*96 + d];
    }
    for (int i = tid; i < DD*MM; i += 256) {
        int d = i >> 6, m = i & 63;
        pT[d*MM + m] = proj[m*DD + d];
    }
    if (tid < 4*DD) {
        int r = tid >> 5, d = tid & 31;
        snode[r*DD + d] = node_emb[(base + r)*DD + d];
    }
    __syncthreads();
    {
        int w = tid >> 5, lane = tid & 31;
        int r = w & 3;
        bool s2 = (w >= 4);
        const float* wt = s2 ? w2t : w1t;
        float bp = s2 ? g_bp2[b*DD + lane] : g_bp1[b*DD + lane];
        float np = 0.f;
#pragma unroll
        for (int d = 0; d < DD; d++) np += snode[r*DD + d] * wt[d*DD + lane];
        float data = (np + bp) * ALPHA;
        (s2 ? sd2 : sd1)[r*DD + lane] = data;
        float sq = data * data;
        for (int o = 16; o; o >>= 1) sq += __shfl_xor_sync(0xffffffffu, sq, o);
        if (lane == 0) (s2 ? sdiag2 : sdiag1)[r] = 0.5f * sq;
    }
    __syncthreads();
    int row = tid >> 6, m = tid & 63;
    float d1 = 0.f, d2 = 0.f;
#pragma unroll
    for (int d = 0; d < DD; d++) {
        float p = pT[d*MM + m];
        d1 += sd1[row*DD + d] * p;
        d2 += sd2[row*DD + d] * p;
    }
    float mx = d1;
    for (int o = 16; o; o >>= 1) mx = fmaxf(mx, __shfl_xor_sync(0xffffffffu, mx, o));
    if ((tid & 31) == 0) swm[tid >> 5] = mx;
    float mk = d2;
    for (int o = 16; o; o >>= 1) mk = fmaxf(mk, __shfl_xor_sync(0xffffffffu, mk, o));
    if ((tid & 31) == 0) swm2[tid >> 5] = mk;
    __syncthreads();
    float qmax = fmaxf(swm[row*2], swm[row*2 + 1]);
    int n = base + row;
    g_phiq[(b*NN + n)*MM + m] = RATIO * (expf(d1 - sdiag1[row] - qmax) + RFEPS);
    g_phik[(b*NN + n)*MM + m] = d2 - sdiag2[row];   // raw; stab applied later
    if (tid == 0) {
        float bm = swm2[0];
#pragma unroll
        for (int i = 1; i < 8; i++) bm = fmaxf(bm, swm2[i]);
        atomicMax(&g_stab[b], fenc(bm));
    }
}

// ---------------- K3: finalize phi_k + ksum ------------------------------
__global__ void k_pkfin() {
    int tid = threadIdx.x, b = blockIdx.y;
    float stab = fdec(g_stab[b]);
    int baseb = b * NN * MM;
    float lsum = 0.f;
    for (int idx = blockIdx.x*256 + tid; idx < NN*MM; idx += gridDim.x*256) {
        float v = RATIO * (expf(g_phik[baseb + idx] - stab) + RFEPS);
        g_phik[baseb + idx] = v;
        lsum += v;
    }
    __shared__ float s[256];
    s[tid] = lsum;
    __syncthreads();
    if (tid < 64)
        atomicAdd(&g_ksum[b*MM + tid], s[tid] + s[tid+64] + s[tid+128] + s[tid+192]);
}

// ---------------- K4: den = phi_q . ksum ---------------------------------
__global__ void k_den() {
    __shared__ float sk[MM];
    __shared__ float sred[8];
    int tid = threadIdx.x, b = blockIdx.y;
    int base = blockIdx.x*4;
    if (tid < MM) sk[tid] = g_ksum[b*MM + tid];
    __syncthreads();
    int row = tid >> 6, m = tid & 63;
    float v = g_phiq[(b*NN + base + row)*MM + m] * sk[m];
    for (int o = 16; o; o >>= 1) v += __shfl_xor_sync(0xffffffffu, v, o);
    if ((tid & 31) == 0) sred[tid >> 5] = v;
    __syncthreads();
    if (tid < 4) g_den[b*NN + base + tid] = sred[tid*2] + sred[tid*2 + 1];
}

// ---------------- per-layer: zero kv -------------------------------------
__global__ void k_zerokv() {
    int i = blockIdx.x*256 + threadIdx.x;
    g_kv[i] = 0.f;
}

// ---------------- per-layer: u = sigmoid(h@in^T+b)*(h@out^T+b) -----------
// 64 rows x (64 gate cols + 64 value cols) per block, K=128 in 4 chunks of 32
__global__ void __launch_bounds__(256) k_ugemm(int li, const float* __restrict__ in_b,
                                               const float* __restrict__ out_b) {
    __shared__ float As[64*36];
    __shared__ float Bg[32*64];
    __shared__ float Bv[32*64];
    int tid = threadIdx.x;
    int b = blockIdx.z, j0 = blockIdx.y*64, row0 = blockIdx.x*64;
    int ty = tid >> 4, tx = tid & 15;
    float gacc[4][4] = {{0}}, vacc[4][4] = {{0}};
    for (int kc = 0; kc < 4; kc++) {
        {
            int lr = tid >> 2, lq = tid & 3;
            int grow = row0 + lr;
#pragma unroll
            for (int h2 = 0; h2 < 2; h2++) {
                int f = lq + h2*4;
                float4 v = make_float4(0.f, 0.f, 0.f, 0.f);
                if (grow < NN) v = *(const float4*)&g_h[(b*NN + grow)*CC + kc*32 + f*4];
                *(float4*)&As[lr*36 + f*4] = v;
            }
        }
        {
            int lk = tid >> 3, lc = tid & 7;
#pragma unroll
            for (int h2 = 0; h2 < 2; h2++) {
                int f = lc + h2*8;
                *(float4*)&Bg[lk*64 + f*4] =
                    *(const float4*)&g_wcomb[li*32768 + (kc*32 + lk)*256 + j0 + f*4];
                *(float4*)&Bv[lk*64 + f*4] =
                    *(const float4*)&g_wcomb[li*32768 + (kc*32 + lk)*256 + j0 + 128 + f*4];
            }
        }
        __syncthreads();
#pragma unroll
        for (int k = 0; k < 32; k++) {
            float a[4];
#pragma unroll
            for (int i2 = 0; i2 < 4; i2++) a[i2] = As[(ty*4 + i2)*36 + k];
            float4 bg = *(float4*)&Bg[k*64 + tx*4];
            float4 bv = *(float4*)&Bv[k*64 + tx*4];
#pragma unroll
            for (int i2 = 0; i2 < 4; i2++) {
                gacc[i2][0] += a[i2]*bg.x; gacc[i2][1] += a[i2]*bg.y;
                gacc[i2][2] += a[i2]*bg.z; gacc[i2][3] += a[i2]*bg.w;
                vacc[i2][0] += a[i2]*bv.x; vacc[i2][1] += a[i2]*bv.y;
                vacc[i2][2] += a[i2]*bv.z; vacc[i2][3] += a[i2]*bv.w;
            }
        }
        __syncthreads();
    }
    float4 ib = *(const float4*)&in_b[li*CC + j0 + tx*4];
    float4 ob = *(const float4*)&out_b[li*CC + j0 + tx*4];
#pragma unroll
    for (int i2 = 0; i2 < 4; i2++) {
        int grow = row0 + ty*4 + i2;
        if (grow < NN) {
            float g0 = gacc[i2][0] + ib.x, g1 = gacc[i2][1] + ib.y;
            float g2 = gacc[i2][2] + ib.z, g3 = gacc[i2][3] + ib.w;
            float v0 = vacc[i2][0] + ob.x, v1 = vacc[i2][1] + ob.y;
            float v2 = vacc[i2][2] + ob.z, v3 = vacc[i2][3] + ob.w;
            float4 o;
            o.x = v0 / (1.f + expf(-g0));
            o.y = v1 / (1.f + expf(-g1));
            o.z = v2 / (1.f + expf(-g2));
            o.w = v3 / (1.f + expf(-g3));
            *(float4*)&g_u[(b*NN + grow)*CC + j0 + tx*4] = o;
        }
    }
}

// ---------------- per-layer: kv = phi_k^T u (block partials + atomics) ---
__global__ void __launch_bounds__(256) k_kv() {
    __shared__ float ph[32*64];
    __shared__ float us[32*128];
    int tid = threadIdx.x, b = blockIdx.y;
    int n0 = blockIdx.x*512;
    int tm = tid >> 4, tc = tid & 15;
    float acc[4][8] = {{0}};
    for (int ch = 0; ch < 16; ch++) {
        int nb = n0 + ch*32;
        int lr = tid >> 3, lf = tid & 7;
        int n = nb + lr;
        float4 z = make_float4(0.f, 0.f, 0.f, 0.f);
#pragma unroll
        for (int h2 = 0; h2 < 2; h2++) {
            int f = lf + h2*8;
            float4 v = z;
            if (n < NN) v = *(const float4*)&g_phik[(b*NN + n)*MM + f*4 - ((f>=16)?64:0)];
            // f in [0,16): first half covers 64 floats exactly
            if (f < 16) *(float4*)&ph[lr*64 + f*4] = v;
        }
#pragma unroll
        for (int h2 = 0; h2 < 4; h2++) {
            int f = lf + h2*8;
            float4 v = z;
            if (n < NN) v = *(const float4*)&g_u[(b*NN + n)*CC + f*4];
            *(float4*)&us[lr*128 + f*4] = v;
        }
        __syncthreads();
#pragma unroll 8
        for (int r = 0; r < 32; r++) {
            float4 pk = *(float4*)&ph[r*64 + tm*4];
            float4 u0 = *(float4*)&us[r*128 + tc*8];
            float4 u1 = *(float4*)&us[r*128 + tc*8 + 4];
            float pp[4] = {pk.x, pk.y, pk.z, pk.w};
            float uu[8] = {u0.x, u0.y, u0.z, u0.w, u1.x, u1.y, u1.z, u1.w};
#pragma unroll
            for (int a = 0; a < 4; a++)
#pragma unroll
                for (int c2 = 0; c2 < 8; c2++) acc[a][c2] += pp[a] * uu[c2];
        }
        __syncthreads();
    }
#pragma unroll
    for (int a = 0; a < 4; a++)
#pragma unroll
        for (int c2 = 0; c2 < 8; c2++)
            atomicAdd(&g_kv[b*MM*CC + (tm*4 + a)*CC + tc*8 + c2], acc[a][c2]);
}

// ---------------- per-layer: num/den + residual + LayerNorm --------------
__global__ void __launch_bounds__(128) k_attn(int li, const float* __restrict__ lng,
                                              const float* __restrict__ lnb) {
    __shared__ float skv[MM*CC];
    __shared__ float sphi[MM];
    __shared__ float ssum[4], ssq[4];
    int tid = threadIdx.x, b = blockIdx.y;
    for (int i = tid; i < MM*CC; i += 128) skv[i] = g_kv[b*MM*CC + i];
    float gamma = lng[li*CC + tid], beta = lnb[li*CC + tid];
    int r0 = blockIdx.x*125;
    for (int it = 0; it < 125; it++) {
        int n = r0 + it;
        __syncthreads();
        if (tid < MM) sphi[tid] = g_phiq[(b*NN + n)*MM + tid];
        __syncthreads();
        float num = 0.f;
#pragma unroll
        for (int m = 0; m < MM; m++) num += sphi[m] * skv[m*CC + tid];
        float val = num / g_den[b*NN + n] + g_h[(b*NN + n)*CC + tid];
        float s = val, q = val*val;
        for (int o = 16; o; o >>= 1) {
            s += __shfl_xor_sync(0xffffffffu, s, o);
            q += __shfl_xor_sync(0xffffffffu, q, o);
        }
        if ((tid & 31) == 0) { ssum[tid >> 5] = s; ssq[tid >> 5] = q; }
        __syncthreads();
        float ts = ssum[0] + ssum[1] + ssum[2] + ssum[3];
        float tq = ssq[0] + ssq[1] + ssq[2] + ssq[3];
        float mu = ts * (1.f/128.f);
        float var = tq * (1.f/128.f) - mu*mu;
        g_h[(b*NN + n)*CC + tid] = (val - mu) * rsqrtf(var + 1e-5f) * gamma + beta;
    }
}

// ---------------- K8: regression head ------------------------------------
__global__ void k_out(const float* __restrict__ reg_w, const float* __restrict__ reg_b,
                      float* __restrict__ out) {
    __shared__ float srw[PP*256];
    __shared__ float srb[PP];
    int tid = threadIdx.x;
    for (int i = tid; i < PP*256; i += 256) srw[i] = reg_w[i];
    if (tid < PP) srb[tid] = reg_b[tid];
    __syncthreads();
    int b = blockIdx.y;
    int n = blockIdx.x*256 + tid;
    if (n >= NN) return;
    float acc[PP];
#pragma unroll
    for (int p = 0; p < PP; p++) acc[p] = srb[p];
    int base = (b*NN + n)*CC;
#pragma unroll 4
    for (int c4 = 0; c4 < CC/4; c4++) {
        float4 s = *(const float4*)&g_skip[base + c4*4];
        float4 h = *(const float4*)&g_h[base + c4*4];
        float sv[4] = {s.x, s.y, s.z, s.w};
        float hv[4] = {h.x, h.y, h.z, h.w};
#pragma unroll
        for (int j = 0; j < 4; j++) {
            int c = c4*4 + j;
#pragma unroll
            for (int p = 0; p < PP; p++)
                acc[p] += sv[j]*srw[p*256 + c] + hv[j]*srw[p*256 + 128 + c];
        }
    }
#pragma unroll
    for (int p = 0; p < PP; p++) out[(b*PP + p)*NN + n] = acc[p];
}

// ---------------- launch --------------------------------------------------
extern "C" void kernel_launch(void* const* d_in, const int* in_sizes, int n_in,
                              void* d_out, int out_size) {
    const float* x        = (const float*)d_in[0];
    const float* xm       = (const float*)d_in[1];
    const float* node_emb = (const float*)d_in[2];
    const float* time_tab = (const float*)d_in[3];
    const float* week_tab = (const float*)d_in[4];
    const float* input_w  = (const float*)d_in[5];
    const float* input_b  = (const float*)d_in[6];
    const float* w1w      = (const float*)d_in[7];
    const float* w1b      = (const float*)d_in[8];
    const float* w2w      = (const float*)d_in[9];
    const float* w2b      = (const float*)d_in[10];
    const float* in_w     = (const float*)d_in[11];
    const float* in_b     = (const float*)d_in[12];
    const float* out_w    = (const float*)d_in[13];
    const float* out_b    = (const float*)d_in[14];
    const float* lng      = (const float*)d_in[15];
    const float* lnb      = (const float*)d_in[16];
    const float* reg_w    = (const float*)d_in[17];
    const float* reg_b    = (const float*)d_in[18];
    const float* proj     = (const float*)d_in[19];

    k_prep<<<1, 256>>>(xm, input_w, input_b, time_tab, week_tab, w1w, w1b, w2w, w2b);
    k_wcomb<<<384, 256>>>(in_w, out_w);
    k_embed<<<dim3(79, 8), 256>>>(x, input_w, node_emb, time_tab, week_tab);
    k_phi<<<dim3(5000, 8), 256>>>(node_emb, w1w, w2w, proj);
    k_pkfin<<<dim3(40, 8), 256>>>();
    k_den<<<dim3(5000, 8), 256>>>();
    for (int li = 0; li < LL; li++) {
        k_zerokv<<<256, 256>>>();
        k_ugemm<<<dim3(313, 2, 8), 256>>>(li, in_b, out_b);
        k_kv<<<dim3(40, 8), 256>>>();
        k_attn<<<dim3(160, 8), 128>>>(li, lng, lnb);
    }
    k_out<<<dim3(79, 8), 256>>>(reg_w, reg_b, (float*)d_out);
}

// round 2
// speedup vs baseline: 2.7968x; 2.7968x over previous
#include <cuda_runtime.h>
#include <math.h>

#define BB 8
#define TT 96
#define NN 20000
#define PP 12
#define LL 3
#define DD 32
#define CC 128
#define MM 64

// ---------------- scratch (static device globals; no dynamic allocation) ----
__device__ float    g_h   [BB*NN*CC];
__device__ float    g_skip[BB*NN*CC];
__device__ float    g_u   [BB*NN*CC];
__device__ float    g_phiq[BB*NN*MM];
__device__ float    g_phik[BB*NN*MM];
__device__ float    g_kv  [BB*MM*CC];
__device__ float    g_ksum[BB*MM];
__device__ unsigned g_stab[BB];
__device__ float    g_cb  [BB*DD];
__device__ float    g_bp1 [BB*DD];
__device__ float    g_bp2 [BB*DD];
__device__ int      g_tod [BB];
__device__ int      g_dow [BB];
__device__ float    g_wcomb[LL*CC*2*CC];   // [layer][k(128)][j(256)]; j<128 gate, j>=128 value

#define ALPHA 0.84089641525371454f   // 2 * 32^(-1/4)
#define RATIO 0.125f                 // 1/sqrt(64)
#define RFEPS 1e-6f

// packed f32x2 helpers (Blackwell): FFMA2 doubles fp32 fma-pipe throughput
#define PK2(d, lo, hi)  asm("mov.b64 %0, {%1,%2};" : "=l"(d) : "f"(lo), "f"(hi))
#define UPK2(lo, hi, s) asm("mov.b64 {%0,%1}, %2;" : "=f"(lo), "=f"(hi) : "l"(s))
#define FMA2(d, a, b)   asm("fma.rn.f32x2 %0, %1, %2, %0;" : "+l"(d) : "l"(a), "l"(b))

__device__ __forceinline__ unsigned fenc(float f) {
    unsigned b = __float_as_uint(f);
    return (b & 0x80000000u) ? ~b : (b | 0x80000000u);
}
__device__ __forceinline__ float fdec(unsigned u) {
    return (u & 0x80000000u) ? __uint_as_float(u ^ 0x80000000u) : __uint_as_float(~u);
}

// ---------------- K0: per-batch constants --------------------------------
__global__ void k_prep(const float* __restrict__ xm, const float* __restrict__ input_w,
                       const float* __restrict__ input_b,
                       const float* __restrict__ time_tab, const float* __restrict__ week_tab,
                       const float* __restrict__ w1w, const float* __restrict__ w1b,
                       const float* __restrict__ w2w, const float* __restrict__ w2b) {
    int tid = threadIdx.x;
    if (tid < BB) {
        float m0 = xm[(tid*TT + TT-1)*2 + 0];
        float m1 = xm[(tid*TT + TT-1)*2 + 1];
        int t = (int)(m0 * (float)TT); t = min(max(t, 0), TT-1);
        int w = (int)(m1 * 7.0f);      w = min(max(w, 0), 6);
        g_tod[tid] = t; g_dow[tid] = w; g_stab[tid] = 0u;
    }
    for (int i = tid; i < BB*MM; i += blockDim.x) g_ksum[i] = 0.f;
    __syncthreads();
    int b = tid >> 5, c = tid & 31;
    float cb = input_b[c];
    for (int t = 0; t < TT; t++) {
        cb += xm[(b*TT + t)*2 + 0] * input_w[c*288 + 96  + t];
        cb += xm[(b*TT + t)*2 + 1] * input_w[c*288 + 192 + t];
    }
    g_cb[b*DD + c] = cb;
    int tod = g_tod[b], dow = g_dow[b];
    float b1 = w1b[c], b2 = w2b[c];
    for (int d = 0; d < DD; d++) {
        float te = time_tab[tod*DD + d], we = week_tab[dow*DD + d];
        b1 += te * w1w[c*96 + 32 + d] + we * w1w[c*96 + 64 + d];
        b2 += te * w2w[c*96 + 32 + d] + we * w2w[c*96 + 64 + d];
    }
    g_bp1[b*DD + c] = b1;
    g_bp2[b*DD + c] = b2;
}

// ---------------- K0b: combined transposed layer weights -----------------
__global__ void k_wcomb(const float* __restrict__ in_w, const float* __restrict__ out_w) {
    int idx = blockIdx.x*256 + threadIdx.x;
    int i = idx / (CC*256);
    int r = idx % (CC*256);
    int k = r >> 8;
    int j = r & 255;
    g_wcomb[idx] = (j < CC) ? in_w[(i*CC + j)*CC + k]
                            : out_w[(i*CC + (j-CC))*CC + k];
}

// ---------------- K1: input embedding + build h / skip -------------------
__global__ void k_embed(const float* __restrict__ x, const float* __restrict__ input_w,
                        const float* __restrict__ node_emb,
                        const float* __restrict__ time_tab, const float* __restrict__ week_tab) {
    __shared__ float wT[TT*DD];
    __shared__ float scb[DD];
    int tid = threadIdx.x, b = blockIdx.y;
    for (int i = tid; i < TT*DD; i += 256) {
        int t = i >> 5, c = i & 31;
        wT[i] = input_w[c*288 + t];
    }
    if (tid < DD) scb[tid] = g_cb[b*DD + tid];
    __syncthreads();
    int n = blockIdx.x*256 + tid;
    if (n >= NN) return;
    float acc[DD];
#pragma unroll
    for (int c = 0; c < DD; c++) acc[c] = scb[c];
    for (int t = 0; t < TT; t++) {
        float xv = x[(b*TT + t)*NN + n];
#pragma unroll
        for (int c = 0; c < DD; c++) acc[c] += xv * wT[t*DD + c];
    }
    int base = (b*NN + n)*CC;
    int tod = g_tod[b], dow = g_dow[b];
#pragma unroll
    for (int q = 0; q < 8; q++) {
        float4 v = make_float4(acc[q*4], acc[q*4+1], acc[q*4+2], acc[q*4+3]);
        *(float4*)&g_h[base + q*4] = v;  *(float4*)&g_skip[base + q*4] = v;
    }
#pragma unroll
    for (int q = 0; q < 8; q++) {
        float4 v = *(const float4*)&node_emb[n*DD + q*4];
        *(float4*)&g_h[base + 32 + q*4] = v;  *(float4*)&g_skip[base + 32 + q*4] = v;
    }
#pragma unroll
    for (int q = 0; q < 8; q++) {
        float4 v = *(const float4*)&time_tab[tod*DD + q*4];
        *(float4*)&g_h[base + 64 + q*4] = v;  *(float4*)&g_skip[base + 64 + q*4] = v;
    }
#pragma unroll
    for (int q = 0; q < 8; q++) {
        float4 v = *(const float4*)&week_tab[dow*DD + q*4];
        *(float4*)&g_h[base + 96 + q*4] = v;  *(float4*)&g_skip[base + 96 + q*4] = v;
    }
}

// ---------------- K2: random-feature maps (64 rows per block) -------------
__global__ void __launch_bounds__(256) k_phi(const float* __restrict__ node_emb,
                      const float* __restrict__ w1w, const float* __restrict__ w2w,
                      const float* __restrict__ proj) {
    __shared__ float w1t[DD*DD], w2t[DD*DD];     // [d][c]
    __shared__ float pm[MM*33];                  // proj rows, padded
    __shared__ float sdp[64*DD*2];               // interleaved {d1,d2} per (row,d)
    __shared__ float sdiag1[64], sdiag2[64];
    __shared__ float smaxq[16*8];
    __shared__ float skm[8];
    int tid = threadIdx.x, b = blockIdx.y;
    int n0 = blockIdx.x*64;
    int lane = tid & 31, w = tid >> 5;
    for (int i = tid; i < DD*DD; i += 256) {
        int c = i >> 5, d = i & 31;
        w1t[d*DD + c] = w1w[c*96 + d];
        w2t[d*DD + c] = w2w[c*96 + d];
    }
    for (int i = tid; i < MM*DD; i += 256) {
        int m = i >> 5, d = i & 31;
        pm[m*33 + d] = proj[i];
    }
    __syncthreads();
    // phase 2: node vectors -> data1/data2 for 64 rows
    {
        float wc1[DD], wc2[DD];
#pragma unroll
        for (int d = 0; d < DD; d++) { wc1[d] = w1t[d*DD + lane]; wc2[d] = w2t[d*DD + lane]; }
        float bp1 = g_bp1[b*DD + lane], bp2 = g_bp2[b*DD + lane];
        for (int it = 0; it < 8; it++) {
            int row = it*8 + w;
            int n = n0 + row;
            float nv = (n < NN) ? node_emb[n*DD + lane] : 0.f;
            float a1 = bp1, a2 = bp2;
#pragma unroll
            for (int d = 0; d < DD; d++) {
                float a = __shfl_sync(0xffffffffu, nv, d);
                a1 += a * wc1[d]; a2 += a * wc2[d];
            }
            a1 *= ALPHA; a2 *= ALPHA;
            *(float2*)&sdp[(row*DD + lane)*2] = make_float2(a1, a2);
            float sq1 = a1*a1, sq2 = a2*a2;
            for (int o = 16; o; o >>= 1) {
                sq1 += __shfl_xor_sync(0xffffffffu, sq1, o);
                sq2 += __shfl_xor_sync(0xffffffffu, sq2, o);
            }
            if (lane == 0) { sdiag1[row] = 0.5f*sq1; sdiag2[row] = 0.5f*sq2; }
        }
    }
    __syncthreads();
    // phase 3: dash = data @ proj^T, row-max (q), global-max (k)
    int m = tid & 63, rg = tid >> 6;
    float p[DD];
#pragma unroll
    for (int d = 0; d < DD; d++) p[d] = pm[m*33 + d];
    float d1v[16], d2v[16];
    float kmax = -3.4e38f;
#pragma unroll
    for (int it = 0; it < 16; it++) {
        int row = it*4 + rg;
        float s1 = 0.f, s2 = 0.f;
#pragma unroll
        for (int d = 0; d < DD; d += 2) {
            float4 sp = *(const float4*)&sdp[(row*DD + d)*2];
            s1 += sp.x*p[d] + sp.z*p[d+1];
            s2 += sp.y*p[d] + sp.w*p[d+1];
        }
        d1v[it] = s1; d2v[it] = s2;
        float mx = s1;
        for (int o = 16; o; o >>= 1) mx = fmaxf(mx, __shfl_xor_sync(0xffffffffu, mx, o));
        if (lane == 0) smaxq[it*8 + w] = mx;
        if (n0 + row < NN) kmax = fmaxf(kmax, s2);
    }
    __syncthreads();
#pragma unroll
    for (int it = 0; it < 16; it++) {
        int row = it*4 + rg;
        int n = n0 + row;
        if (n < NN) {
            float qmax = fmaxf(smaxq[it*8 + rg*2], smaxq[it*8 + rg*2 + 1]);
            g_phiq[(b*NN + n)*MM + m] = RATIO*(expf(d1v[it] - sdiag1[row] - qmax) + RFEPS);
            g_phik[(b*NN + n)*MM + m] = d2v[it] - sdiag2[row];
        }
    }
    for (int o = 16; o; o >>= 1) kmax = fmaxf(kmax, __shfl_xor_sync(0xffffffffu, kmax, o));
    if (lane == 0) skm[w] = kmax;
    __syncthreads();
    if (tid == 0) {
        float bm = skm[0];
#pragma unroll
        for (int i = 1; i < 8; i++) bm = fmaxf(bm, skm[i]);
        atomicMax(&g_stab[b], fenc(bm));
    }
}

// ---------------- K3: finalize phi_k + ksum ------------------------------
__global__ void k_pkfin() {
    int tid = threadIdx.x, b = blockIdx.y;
    float stab = fdec(g_stab[b]);
    int baseb = b * NN * MM;
    float lsum = 0.f;
    for (int idx = blockIdx.x*256 + tid; idx < NN*MM; idx += gridDim.x*256) {
        float v = RATIO * (expf(g_phik[baseb + idx] - stab) + RFEPS);
        g_phik[baseb + idx] = v;
        lsum += v;
    }
    __shared__ float s[256];
    s[tid] = lsum;
    __syncthreads();
    if (tid < 64)
        atomicAdd(&g_ksum[b*MM + tid], s[tid] + s[tid+64] + s[tid+128] + s[tid+192]);
}

// ---------------- per-layer: zero kv -------------------------------------
__global__ void k_zerokv() {
    int i = blockIdx.x*256 + threadIdx.x;
    g_kv[i] = 0.f;
}

// ---------------- per-layer: u = sigmoid(h@in^T+b)*(h@out^T+b) -----------
// 128 rows x 64 j-pairs per block; FFMA2 over j-col pairs
__global__ void __launch_bounds__(256, 2) k_ugemm(int li, const float* __restrict__ in_b,
                                                  const float* __restrict__ out_b) {
    __shared__ float As[128*20];
    __shared__ float Bg[16*64];
    __shared__ float Bv[16*64];
    int tid = threadIdx.x;
    int b = blockIdx.z, j0 = blockIdx.y*64, row0 = blockIdx.x*128;
    int tx = tid & 15, ty = tid >> 4;
    unsigned long long ag[8][2], av[8][2];
#pragma unroll
    for (int r = 0; r < 8; r++) { ag[r][0]=0ull; ag[r][1]=0ull; av[r][0]=0ull; av[r][1]=0ull; }
    int lr = tid >> 1, lq = tid & 1;
    int lk = tid >> 4, lj = tid & 15;
    for (int kc = 0; kc < 8; kc++) {
        {
            int grow = row0 + lr;
            float4 v0 = make_float4(0.f,0.f,0.f,0.f), v1 = v0;
            if (grow < NN) {
                const float4* src = (const float4*)&g_h[(b*NN + grow)*CC + kc*16 + lq*8];
                v0 = src[0]; v1 = src[1];
            }
            *(float4*)&As[lr*20 + lq*8]     = v0;
            *(float4*)&As[lr*20 + lq*8 + 4] = v1;
        }
        {
            const float* wb = &g_wcomb[li*32768 + (kc*16 + lk)*256 + j0];
            *(float4*)&Bg[lk*64 + lj*4] = *(const float4*)&wb[lj*4];
            *(float4*)&Bv[lk*64 + lj*4] = *(const float4*)&wb[128 + lj*4];
        }
        __syncthreads();
#pragma unroll
        for (int k = 0; k < 16; k++) {
            float4 bg = *(float4*)&Bg[k*64 + tx*4];
            float4 bv = *(float4*)&Bv[k*64 + tx*4];
            unsigned long long bg0, bg1, bv0, bv1;
            PK2(bg0, bg.x, bg.y); PK2(bg1, bg.z, bg.w);
            PK2(bv0, bv.x, bv.y); PK2(bv1, bv.z, bv.w);
#pragma unroll
            for (int r = 0; r < 8; r++) {
                float a = As[(ty*8 + r)*20 + k];
                unsigned long long a2; PK2(a2, a, a);
                FMA2(ag[r][0], a2, bg0); FMA2(ag[r][1], a2, bg1);
                FMA2(av[r][0], a2, bv0); FMA2(av[r][1], a2, bv1);
            }
        }
        __syncthreads();
    }
    float4 ib = *(const float4*)&in_b[li*CC + j0 + tx*4];
    float4 ob = *(const float4*)&out_b[li*CC + j0 + tx*4];
#pragma unroll
    for (int r = 0; r < 8; r++) {
        int grow = row0 + ty*8 + r;
        if (grow < NN) {
            float gg0,gg1,gg2,gg3,vv0,vv1,vv2,vv3;
            UPK2(gg0, gg1, ag[r][0]); UPK2(gg2, gg3, ag[r][1]);
            UPK2(vv0, vv1, av[r][0]); UPK2(vv2, vv3, av[r][1]);
            gg0 += ib.x; gg1 += ib.y; gg2 += ib.z; gg3 += ib.w;
            vv0 += ob.x; vv1 += ob.y; vv2 += ob.z; vv3 += ob.w;
            float4 o;
            o.x = vv0 / (1.f + expf(-gg0));
            o.y = vv1 / (1.f + expf(-gg1));
            o.z = vv2 / (1.f + expf(-gg2));
            o.w = vv3 / (1.f + expf(-gg3));
            *(float4*)&g_u[(b*NN + grow)*CC + j0 + tx*4] = o;
        }
    }
}

// ---------------- per-layer: kv = phi_k^T u (block partials + atomics) ---
__global__ void __launch_bounds__(256) k_kv() {
    __shared__ float ph[32*64];
    __shared__ float us[32*128];
    int tid = threadIdx.x, b = blockIdx.y;
    int n0 = blockIdx.x*512;
    int tm = tid >> 4, tc = tid & 15;
    unsigned long long acc[4][4];
#pragma unroll
    for (int a = 0; a < 4; a++)
#pragma unroll
        for (int c = 0; c < 4; c++) acc[a][c] = 0ull;
    for (int ch = 0; ch < 16; ch++) {
        int nb = n0 + ch*32;
        int lr = tid >> 3, lf = tid & 7;
        int n = nb + lr;
        float4 z = make_float4(0.f, 0.f, 0.f, 0.f);
#pragma unroll
        for (int h2 = 0; h2 < 2; h2++) {
            int f = lf + h2*8;
            float4 v = z;
            if (n < NN) v = *(const float4*)&g_phik[(b*NN + n)*MM + f*4];
            *(float4*)&ph[lr*64 + f*4] = v;
        }
#pragma unroll
        for (int h2 = 0; h2 < 4; h2++) {
            int f = lf + h2*8;
            float4 v = z;
            if (n < NN) v = *(const float4*)&g_u[(b*NN + n)*CC + f*4];
            *(float4*)&us[lr*128 + f*4] = v;
        }
        __syncthreads();
#pragma unroll 8
        for (int r = 0; r < 32; r++) {
            float4 pk = *(float4*)&ph[r*64 + tm*4];
            float4 u0 = *(float4*)&us[r*128 + tc*8];
            float4 u1 = *(float4*)&us[r*128 + tc*8 + 4];
            unsigned long long up0, up1, up2, up3;
            PK2(up0, u0.x, u0.y); PK2(up1, u0.z, u0.w);
            PK2(up2, u1.x, u1.y); PK2(up3, u1.z, u1.w);
            unsigned long long a2;
            PK2(a2, pk.x, pk.x);
            FMA2(acc[0][0], a2, up0); FMA2(acc[0][1], a2, up1);
            FMA2(acc[0][2], a2, up2); FMA2(acc[0][3], a2, up3);
            PK2(a2, pk.y, pk.y);
            FMA2(acc[1][0], a2, up0); FMA2(acc[1][1], a2, up1);
            FMA2(acc[1][2], a2, up2); FMA2(acc[1][3], a2, up3);
            PK2(a2, pk.z, pk.z);
            FMA2(acc[2][0], a2, up0); FMA2(acc[2][1], a2, up1);
            FMA2(acc[2][2], a2, up2); FMA2(acc[2][3], a2, up3);
            PK2(a2, pk.w, pk.w);
            FMA2(acc[3][0], a2, up0); FMA2(acc[3][1], a2, up1);
            FMA2(acc[3][2], a2, up2); FMA2(acc[3][3], a2, up3);
        }
        __syncthreads();
    }
#pragma unroll
    for (int a = 0; a < 4; a++)
#pragma unroll
        for (int cp = 0; cp < 4; cp++) {
            float lo, hi;
            UPK2(lo, hi, acc[a][cp]);
            atomicAdd(&g_kv[b*MM*CC + (tm*4 + a)*CC + tc*8 + cp*2],     lo);
            atomicAdd(&g_kv[b*MM*CC + (tm*4 + a)*CC + tc*8 + cp*2 + 1], hi);
        }
}

// ---------------- per-layer: num/den + residual + LayerNorm (GEMM-style) --
// 64 rows x 128 cols per block; den computed in-block; LN warp-local
__global__ void __launch_bounds__(256) k_attn(int li, const float* __restrict__ lng,
                                              const float* __restrict__ lnb) {
    __shared__ float skv[MM*CC];    // 32KB
    __shared__ float sphi[64*MM];   // 16KB
    __shared__ float sk[MM];
    __shared__ float sden[64];
    int tid = threadIdx.x, b = blockIdx.y;
    int r0 = blockIdx.x*64;
    for (int i = tid; i < MM*CC/4; i += 256)
        *(float4*)&skv[i*4] = *(const float4*)&g_kv[b*MM*CC + i*4];
    for (int i = tid; i < 64*MM/4; i += 256) {
        int row = (i*4) >> 6;
        float4 v = make_float4(0.f,0.f,0.f,0.f);
        if (r0 + row < NN) v = *(const float4*)&g_phiq[(b*NN + r0)*MM + i*4];
        *(float4*)&sphi[i*4] = v;
    }
    if (tid < MM) sk[tid] = g_ksum[b*MM + tid];
    __syncthreads();
    int tx = tid & 31, w = tid >> 5;
    // den for this block's rows (8 per warp)
#pragma unroll
    for (int i = 0; i < 8; i++) {
        int row = w*8 + i;
        float v = sphi[row*MM + tx]*sk[tx] + sphi[row*MM + 32 + tx]*sk[32 + tx];
        for (int o = 16; o; o >>= 1) v += __shfl_xor_sync(0xffffffffu, v, o);
        if (tx == 0) sden[row] = v;
    }
    __syncthreads();
    unsigned long long acc[8][2];
#pragma unroll
    for (int i = 0; i < 8; i++) { acc[i][0] = 0ull; acc[i][1] = 0ull; }
    for (int m = 0; m < MM; m++) {
        float4 kv4 = *(float4*)&skv[m*CC + tx*4];
        unsigned long long k0, k1;
        PK2(k0, kv4.x, kv4.y); PK2(k1, kv4.z, kv4.w);
#pragma unroll
        for (int i = 0; i < 8; i++) {
            float a = sphi[(w*8 + i)*MM + m];
            unsigned long long a2; PK2(a2, a, a);
            FMA2(acc[i][0], a2, k0); FMA2(acc[i][1], a2, k1);
        }
    }
    float4 gam = *(const float4*)&lng[li*CC + tx*4];
    float4 bet = *(const float4*)&lnb[li*CC + tx*4];
#pragma unroll
    for (int i = 0; i < 8; i++) {
        int n = r0 + w*8 + i;
        if (n >= NN) continue;
        float x0, x1, x2, x3;
        UPK2(x0, x1, acc[i][0]); UPK2(x2, x3, acc[i][1]);
        float invd = 1.f / sden[w*8 + i];
        float4 h4 = *(const float4*)&g_h[(b*NN + n)*CC + tx*4];
        x0 = x0*invd + h4.x; x1 = x1*invd + h4.y;
        x2 = x2*invd + h4.z; x3 = x3*invd + h4.w;
        float s = x0 + x1 + x2 + x3;
        float q = x0*x0 + x1*x1 + x2*x2 + x3*x3;
        for (int o = 16; o; o >>= 1) {
            s += __shfl_xor_sync(0xffffffffu, s, o);
            q += __shfl_xor_sync(0xffffffffu, q, o);
        }
        float mu = s * (1.f/128.f);
        float var = q * (1.f/128.f) - mu*mu;
        float rs = rsqrtf(var + 1e-5f);
        float4 o4;
        o4.x = (x0 - mu)*rs*gam.x + bet.x;
        o4.y = (x1 - mu)*rs*gam.y + bet.y;
        o4.z = (x2 - mu)*rs*gam.z + bet.z;
        o4.w = (x3 - mu)*rs*gam.w + bet.w;
        *(float4*)&g_h[(b*NN + n)*CC + tx*4] = o4;
    }
}

// ---------------- K8: regression head ------------------------------------
__global__ void k_out(const float* __restrict__ reg_w, const float* __restrict__ reg_b,
                      float* __restrict__ out) {
    __shared__ float srw[PP*256];
    __shared__ float srb[PP];
    int tid = threadIdx.x;
    for (int i = tid; i < PP*256; i += 256) srw[i] = reg_w[i];
    if (tid < PP) srb[tid] = reg_b[tid];
    __syncthreads();
    int b = blockIdx.y;
    int n = blockIdx.x*256 + tid;
    if (n >= NN) return;
    float acc[PP];
#pragma unroll
    for (int p = 0; p < PP; p++) acc[p] = srb[p];
    int base = (b*NN + n)*CC;
#pragma unroll 4
    for (int c4 = 0; c4 < CC/4; c4++) {
        float4 s = *(const float4*)&g_skip[base + c4*4];
        float4 h = *(const float4*)&g_h[base + c4*4];
        float sv[4] = {s.x, s.y, s.z, s.w};
        float hv[4] = {h.x, h.y, h.z, h.w};
#pragma unroll
        for (int j = 0; j < 4; j++) {
            int c = c4*4 + j;
#pragma unroll
            for (int p = 0; p < PP; p++)
                acc[p] += sv[j]*srw[p*256 + c] + hv[j]*srw[p*256 + 128 + c];
        }
    }
#pragma unroll
    for (int p = 0; p < PP; p++) out[(b*PP + p)*NN + n] = acc[p];
}

// ---------------- launch --------------------------------------------------
extern "C" void kernel_launch(void* const* d_in, const int* in_sizes, int n_in,
                              void* d_out, int out_size) {
    const float* x        = (const float*)d_in[0];
    const float* xm       = (const float*)d_in[1];
    const float* node_emb = (const float*)d_in[2];
    const float* time_tab = (const float*)d_in[3];
    const float* week_tab = (const float*)d_in[4];
    const float* input_w  = (const float*)d_in[5];
    const float* input_b  = (const float*)d_in[6];
    const float* w1w      = (const float*)d_in[7];
    const float* w1b      = (const float*)d_in[8];
    const float* w2w      = (const float*)d_in[9];
    const float* w2b      = (const float*)d_in[10];
    const float* in_w     = (const float*)d_in[11];
    const float* in_b     = (const float*)d_in[12];
    const float* out_w    = (const float*)d_in[13];
    const float* out_b    = (const float*)d_in[14];
    const float* lng      = (const float*)d_in[15];
    const float* lnb      = (const float*)d_in[16];
    const float* reg_w    = (const float*)d_in[17];
    const float* reg_b    = (const float*)d_in[18];
    const float* proj     = (const float*)d_in[19];

    k_prep<<<1, 256>>>(xm, input_w, input_b, time_tab, week_tab, w1w, w1b, w2w, w2b);
    k_wcomb<<<384, 256>>>(in_w, out_w);
    k_embed<<<dim3(79, 8), 256>>>(x, input_w, node_emb, time_tab, week_tab);
    k_phi<<<dim3(313, 8), 256>>>(node_emb, w1w, w2w, proj);
    k_pkfin<<<dim3(40, 8), 256>>>();
    for (int li = 0; li < LL; li++) {
        k_zerokv<<<256, 256>>>();
        k_ugemm<<<dim3(157, 2, 8), 256>>>(li, in_b, out_b);
        k_kv<<<dim3(40, 8), 256>>>();
        k_attn<<<dim3(313, 8), 256>>>(li, lng, lnb);
    }
    k_out<<<dim3(79, 8), 256>>>(reg_w, reg_b, (float*)d_out);
}

// round 4
// speedup vs baseline: 3.3718x; 1.2056x over previous
#include <cuda_runtime.h>
#include <math.h>

#define BB 8
#define TT 96
#define NN 20000
#define PP 12
#define LL 3
#define DD 32
#define CC 128
#define MM 64

// ---------------- scratch (static device globals; no dynamic allocation) ----
__device__ float    g_h   [BB*NN*CC];
__device__ float    g_skip[BB*NN*CC];
__device__ float    g_u   [BB*NN*CC];
__device__ float    g_phiq[BB*NN*MM];
__device__ float    g_phik[BB*NN*MM];
__device__ float    g_kv  [BB*MM*CC];
__device__ float    g_ksum[BB*MM];
__device__ unsigned g_stab[BB];
__device__ float    g_cb  [BB*DD];
__device__ float    g_bp1 [BB*DD];
__device__ float    g_bp2 [BB*DD];
__device__ int      g_tod [BB];
__device__ int      g_dow [BB];
// fragment-major tf32 weights: [layer][ks(16)][nt(32)][lane(32)][2]
__device__ float    g_wcomb[LL*2*CC*CC];

#define ALPHA 0.84089641525371454f   // 2 * 32^(-1/4)
#define RATIO 0.125f                 // 1/sqrt(64)
#define RFEPS 1e-6f

// packed f32x2 helpers
#define PK2(d, lo, hi)  asm("mov.b64 %0, {%1,%2};" : "=l"(d) : "f"(lo), "f"(hi))
#define UPK2(lo, hi, s) asm("mov.b64 {%0,%1}, %2;" : "=f"(lo), "=f"(hi) : "l"(s))
#define FMA2(d, a, b)   asm("fma.rn.f32x2 %0, %1, %2, %0;" : "+l"(d) : "l"(a), "l"(b))

// tf32 tensor-core mma (legacy PTX path; valid for compute_103)
#define MMA_TF32(d, a, b) \
    asm volatile("mma.sync.aligned.m16n8k8.row.col.f32.tf32.tf32.f32 " \
        "{%0,%1,%2,%3}, {%4,%5,%6,%7}, {%8,%9}, {%0,%1,%2,%3};" \
        : "+f"((d)[0]), "+f"((d)[1]), "+f"((d)[2]), "+f"((d)[3]) \
        : "r"((a)[0]), "r"((a)[1]), "r"((a)[2]), "r"((a)[3]), "r"((b).x), "r"((b).y))

__device__ __forceinline__ unsigned fenc(float f) {
    unsigned b = __float_as_uint(f);
    return (b & 0x80000000u) ? ~b : (b | 0x80000000u);
}
__device__ __forceinline__ float fdec(unsigned u) {
    return (u & 0x80000000u) ? __uint_as_float(u ^ 0x80000000u) : __uint_as_float(~u);
}
__device__ __forceinline__ unsigned f2tf32(float x) {
    unsigned r;
    asm("cvt.rna.tf32.f32 %0, %1;" : "=r"(r) : "f"(x));
    return r;
}

// ---------------- K0: per-batch constants --------------------------------
__global__ void k_prep(const float* __restrict__ xm, const float* __restrict__ input_w,
                       const float* __restrict__ input_b,
                       const float* __restrict__ time_tab, const float* __restrict__ week_tab,
                       const float* __restrict__ w1w, const float* __restrict__ w1b,
                       const float* __restrict__ w2w, const float* __restrict__ w2b) {
    int tid = threadIdx.x;
    if (tid < BB) {
        float m0 = xm[(tid*TT + TT-1)*2 + 0];
        float m1 = xm[(tid*TT + TT-1)*2 + 1];
        int t = (int)(m0 * (float)TT); t = min(max(t, 0), TT-1);
        int w = (int)(m1 * 7.0f);      w = min(max(w, 0), 6);
        g_tod[tid] = t; g_dow[tid] = w; g_stab[tid] = 0u;
    }
    for (int i = tid; i < BB*MM; i += blockDim.x) g_ksum[i] = 0.f;
    __syncthreads();
    int b = tid >> 5, c = tid & 31;
    float cb = input_b[c];
    for (int t = 0; t < TT; t++) {
        cb += xm[(b*TT + t)*2 + 0] * input_w[c*288 + 96  + t];
        cb += xm[(b*TT + t)*2 + 1] * input_w[c*288 + 192 + t];
    }
    g_cb[b*DD + c] = cb;
    int tod = g_tod[b], dow = g_dow[b];
    float b1 = w1b[c], b2 = w2b[c];
    for (int d = 0; d < DD; d++) {
        float te = time_tab[tod*DD + d], we = week_tab[dow*DD + d];
        b1 += te * w1w[c*96 + 32 + d] + we * w1w[c*96 + 64 + d];
        b2 += te * w2w[c*96 + 32 + d] + we * w2w[c*96 + 64 + d];
    }
    g_bp1[b*DD + c] = b1;
    g_bp2[b*DD + c] = b2;
}

// ---------------- K0b: combined layer weights, fragment-major tf32 -------
// element: value[i] at (ks, nt, lane): n = nt*8 + lane>>2, k = ks*8 + (lane&3) + i*4
__global__ void k_wcomb(const float* __restrict__ in_w, const float* __restrict__ out_w) {
    int idx = blockIdx.x*256 + threadIdx.x;          // < 3*32768
    int l = idx / 32768;
    int r = idx % 32768;
    int ks   = r >> 11;
    int nt   = (r >> 6) & 31;
    int lane = (r >> 1) & 31;
    int i    = r & 1;
    int n = nt*8 + (lane >> 2);
    int k = ks*8 + (lane & 3) + i*4;
    float v = (n < CC) ? in_w[(l*CC + n)*CC + k]
                       : out_w[(l*CC + n - CC)*CC + k];
    g_wcomb[idx] = __uint_as_float(f2tf32(v));
}

// ---------------- K1: input embedding + build h / skip -------------------
__global__ void k_embed(const float* __restrict__ x, const float* __restrict__ input_w,
                        const float* __restrict__ node_emb,
                        const float* __restrict__ time_tab, const float* __restrict__ week_tab) {
    __shared__ float wT[TT*DD];
    __shared__ float scb[DD];
    int tid = threadIdx.x, b = blockIdx.y;
    for (int i = tid; i < TT*DD; i += 256) {
        int t = i >> 5, c = i & 31;
        wT[i] = input_w[c*288 + t];
    }
    if (tid < DD) scb[tid] = g_cb[b*DD + tid];
    __syncthreads();
    int n = blockIdx.x*256 + tid;
    if (n >= NN) return;
    float acc[DD];
#pragma unroll
    for (int c = 0; c < DD; c++) acc[c] = scb[c];
    for (int t = 0; t < TT; t++) {
        float xv = x[(b*TT + t)*NN + n];
#pragma unroll
        for (int c = 0; c < DD; c++) acc[c] += xv * wT[t*DD + c];
    }
    int base = (b*NN + n)*CC;
    int tod = g_tod[b], dow = g_dow[b];
#pragma unroll
    for (int q = 0; q < 8; q++) {
        float4 v = make_float4(acc[q*4], acc[q*4+1], acc[q*4+2], acc[q*4+3]);
        *(float4*)&g_h[base + q*4] = v;  *(float4*)&g_skip[base + q*4] = v;
    }
#pragma unroll
    for (int q = 0; q < 8; q++) {
        float4 v = *(const float4*)&node_emb[n*DD + q*4];
        *(float4*)&g_h[base + 32 + q*4] = v;  *(float4*)&g_skip[base + 32 + q*4] = v;
    }
#pragma unroll
    for (int q = 0; q < 8; q++) {
        float4 v = *(const float4*)&time_tab[tod*DD + q*4];
        *(float4*)&g_h[base + 64 + q*4] = v;  *(float4*)&g_skip[base + 64 + q*4] = v;
    }
#pragma unroll
    for (int q = 0; q < 8; q++) {
        float4 v = *(const float4*)&week_tab[dow*DD + q*4];
        *(float4*)&g_h[base + 96 + q*4] = v;  *(float4*)&g_skip[base + 96 + q*4] = v;
    }
}

// ---------------- K2: random-feature maps (64 rows per block, chunked) ----
__global__ void __launch_bounds__(256) k_phi(const float* __restrict__ node_emb,
                      const float* __restrict__ w1w, const float* __restrict__ w2w,
                      const float* __restrict__ proj) {
    __shared__ float w1t[DD*DD], w2t[DD*DD];
    __shared__ float pm[MM*33];
    __shared__ float sdp[64*DD*2];
    __shared__ float sdiag1[64], sdiag2[64];
    __shared__ float smaxq[16*8];
    __shared__ float skm[8];
    int tid = threadIdx.x, b = blockIdx.y;
    int n0 = blockIdx.x*64;
    int lane = tid & 31, w = tid >> 5;
    for (int i = tid; i < DD*DD; i += 256) {
        int c = i >> 5, d = i & 31;
        w1t[d*DD + c] = w1w[c*96 + d];
        w2t[d*DD + c] = w2w[c*96 + d];
    }
    for (int i = tid; i < MM*DD; i += 256) {
        int m = i >> 5, d = i & 31;
        pm[m*33 + d] = proj[i];
    }
    __syncthreads();
    {
        float wc1[DD], wc2[DD];
#pragma unroll
        for (int d = 0; d < DD; d++) { wc1[d] = w1t[d*DD + lane]; wc2[d] = w2t[d*DD + lane]; }
        float bp1 = g_bp1[b*DD + lane], bp2 = g_bp2[b*DD + lane];
        for (int it = 0; it < 8; it++) {
            int row = it*8 + w;
            int n = n0 + row;
            float nv = (n < NN) ? node_emb[n*DD + lane] : 0.f;
            float a1 = bp1, a2 = bp2;
#pragma unroll
            for (int d = 0; d < DD; d++) {
                float a = __shfl_sync(0xffffffffu, nv, d);
                a1 += a * wc1[d]; a2 += a * wc2[d];
            }
            a1 *= ALPHA; a2 *= ALPHA;
            *(float2*)&sdp[(row*DD + lane)*2] = make_float2(a1, a2);
            float sq1 = a1*a1, sq2 = a2*a2;
            for (int o = 16; o; o >>= 1) {
                sq1 += __shfl_xor_sync(0xffffffffu, sq1, o);
                sq2 += __shfl_xor_sync(0xffffffffu, sq2, o);
            }
            if (lane == 0) { sdiag1[row] = 0.5f*sq1; sdiag2[row] = 0.5f*sq2; }
        }
    }
    __syncthreads();
    int m = tid & 63, rg = tid >> 6;
    float p[DD];
#pragma unroll
    for (int d = 0; d < DD; d++) p[d] = pm[m*33 + d];
    float kmax = -3.4e38f;
#pragma unroll
    for (int ch = 0; ch < 4; ch++) {
        float d1v[4], d2v[4];
#pragma unroll
        for (int i2 = 0; i2 < 4; i2++) {
            int it = ch*4 + i2;
            int row = it*4 + rg;
            float s1 = 0.f, s2 = 0.f;
#pragma unroll
            for (int d = 0; d < DD; d += 2) {
                float4 sp = *(const float4*)&sdp[(row*DD + d)*2];
                s1 += sp.x*p[d] + sp.z*p[d+1];
                s2 += sp.y*p[d] + sp.w*p[d+1];
            }
            d1v[i2] = s1; d2v[i2] = s2;
            float mx = s1;
            for (int o = 16; o; o >>= 1) mx = fmaxf(mx, __shfl_xor_sync(0xffffffffu, mx, o));
            if (lane == 0) smaxq[it*8 + w] = mx;
            if (n0 + row < NN) kmax = fmaxf(kmax, s2);
        }
        __syncthreads();
#pragma unroll
        for (int i2 = 0; i2 < 4; i2++) {
            int it = ch*4 + i2;
            int row = it*4 + rg;
            int n = n0 + row;
            if (n < NN) {
                float qmax = fmaxf(smaxq[it*8 + rg*2], smaxq[it*8 + rg*2 + 1]);
                g_phiq[(b*NN + n)*MM + m] = RATIO*(expf(d1v[i2] - sdiag1[row] - qmax) + RFEPS);
                g_phik[(b*NN + n)*MM + m] = d2v[i2] - sdiag2[row];
            }
        }
    }
    for (int o = 16; o; o >>= 1) kmax = fmaxf(kmax, __shfl_xor_sync(0xffffffffu, kmax, o));
    if (lane == 0) skm[w] = kmax;
    __syncthreads();
    if (tid == 0) {
        float bm = skm[0];
#pragma unroll
        for (int i = 1; i < 8; i++) bm = fmaxf(bm, skm[i]);
        atomicMax(&g_stab[b], fenc(bm));
    }
}

// ---------------- K3: finalize phi_k + ksum ------------------------------
__global__ void k_pkfin() {
    int tid = threadIdx.x, b = blockIdx.y;
    float stab = fdec(g_stab[b]);
    int baseb = b * NN * MM;
    float lsum = 0.f;
    for (int idx = blockIdx.x*256 + tid; idx < NN*MM; idx += gridDim.x*256) {
        float v = RATIO * (expf(g_phik[baseb + idx] - stab) + RFEPS);
        g_phik[baseb + idx] = v;
        lsum += v;
    }
    __shared__ float s[256];
    s[tid] = lsum;
    __syncthreads();
    if (tid < 64)
        atomicAdd(&g_ksum[b*MM + tid], s[tid] + s[tid+64] + s[tid+128] + s[tid+192]);
}

// ---------------- per-layer: zero kv -------------------------------------
__global__ void k_zerokv() {
    int i = blockIdx.x*256 + threadIdx.x;
    g_kv[i] = 0.f;
}

// ---------------- per-layer: tf32 mma.sync gated GEMM --------------------
// block: 64 rows x 256 cols (128 gate + 128 value), K=128.
// 8 warps along N (32 cols each = 4 n8-tiles); each warp all 4 m16-tiles.
__global__ void __launch_bounds__(256) k_ugemm_mma(int li, const float* __restrict__ in_b,
                                                   const float* __restrict__ out_b) {
    __shared__ float As[64*132];       // A tf32 staged, pad 132; reused as value/u tile
    __shared__ float sbias[256];
    int tid = threadIdx.x, lane = tid & 31, w = tid >> 5;
    int b = blockIdx.y, row0 = blockIdx.x*64;
    if (tid < 128) sbias[tid] = in_b[li*CC + tid];
    else           sbias[tid] = out_b[li*CC + tid - 128];
    // stage A: 64 rows x 128 cols, fp32 -> tf32, row-major pad 132
#pragma unroll
    for (int i = 0; i < 8; i++) {
        int chunk = i*256 + tid;            // row(64) x c4(32)
        int row = chunk >> 5, c4 = chunk & 31;
        int grow = row0 + row;
        float4 v = make_float4(0.f, 0.f, 0.f, 0.f);
        if (grow < NN) v = *(const float4*)&g_h[(b*NN + grow)*CC + c4*4];
        uint4 t;
        t.x = f2tf32(v.x); t.y = f2tf32(v.y); t.z = f2tf32(v.z); t.w = f2tf32(v.w);
        *(uint4*)&As[row*132 + c4*4] = t;
    }
    __syncthreads();
    float acc[4][4][4];
#pragma unroll
    for (int mt = 0; mt < 4; mt++)
#pragma unroll
        for (int q = 0; q < 4; q++)
#pragma unroll
            for (int f = 0; f < 4; f++) acc[mt][q][f] = 0.f;
    const float* wB = &g_wcomb[li*32768];
    int g = lane >> 2, c = lane & 3;
    uint2 bf[4];
#pragma unroll
    for (int q = 0; q < 4; q++)
        bf[q] = *(const uint2*)&wB[(w*4 + q)*64 + lane*2];
#pragma unroll
    for (int ks = 0; ks < 16; ks++) {
        uint2 bn[4];
        if (ks < 15) {
#pragma unroll
            for (int q = 0; q < 4; q++)
                bn[q] = *(const uint2*)&wB[(ks + 1)*2048 + (w*4 + q)*64 + lane*2];
        }
        unsigned a[4][4];
#pragma unroll
        for (int mt = 0; mt < 4; mt++) {
            const float* ap = &As[(mt*16 + g)*132 + ks*8 + c];
            a[mt][0] = __float_as_uint(ap[0]);
            a[mt][1] = __float_as_uint(ap[8*132]);
            a[mt][2] = __float_as_uint(ap[4]);
            a[mt][3] = __float_as_uint(ap[8*132 + 4]);
        }
#pragma unroll
        for (int mt = 0; mt < 4; mt++)
#pragma unroll
            for (int q = 0; q < 4; q++)
                MMA_TF32(acc[mt][q], a[mt], bf[q]);
#pragma unroll
        for (int q = 0; q < 4; q++) bf[q] = bn[q];
    }
    __syncthreads();   // A data dead; reuse As as value tile
    int c2 = c*2;
    if (w >= 4) {      // value warps: stash biased value accums
        int wj = (w - 4)*32;
#pragma unroll
        for (int mt = 0; mt < 4; mt++)
#pragma unroll
            for (int q = 0; q < 4; q++) {
                int col = wj + q*8 + c2;
                float b0 = sbias[128 + col], b1 = sbias[128 + col + 1];
                *(float2*)&As[(mt*16 + g)*132 + col] =
                    make_float2(acc[mt][q][0] + b0, acc[mt][q][1] + b1);
                *(float2*)&As[(mt*16 + g + 8)*132 + col] =
                    make_float2(acc[mt][q][2] + b0, acc[mt][q][3] + b1);
            }
    }
    __syncthreads();
    if (w < 4) {       // gate warps: sigmoid(gate) * value, in place
        int wj = w*32;
#pragma unroll
        for (int mt = 0; mt < 4; mt++)
#pragma unroll
            for (int q = 0; q < 4; q++) {
                int col = wj + q*8 + c2;
                float b0 = sbias[col], b1 = sbias[col + 1];
                float g0 = acc[mt][q][0] + b0, g1 = acc[mt][q][1] + b1;
                float g2 = acc[mt][q][2] + b0, g3 = acc[mt][q][3] + b1;
                float2 v01 = *(float2*)&As[(mt*16 + g)*132 + col];
                float2 v23 = *(float2*)&As[(mt*16 + g + 8)*132 + col];
                *(float2*)&As[(mt*16 + g)*132 + col] =
                    make_float2(v01.x/(1.f + expf(-g0)), v01.y/(1.f + expf(-g1)));
                *(float2*)&As[(mt*16 + g + 8)*132 + col] =
                    make_float2(v23.x/(1.f + expf(-g2)), v23.y/(1.f + expf(-g3)));
            }
    }
    __syncthreads();
#pragma unroll
    for (int i = 0; i < 8; i++) {
        int chunk = i*256 + tid;
        int row = chunk >> 5, c4 = chunk & 31;
        int grow = row0 + row;
        if (grow < NN)
            *(float4*)&g_u[(b*NN + grow)*CC + c4*4] = *(float4*)&As[row*132 + c4*4];
    }
}

// ---------------- per-layer: kv = phi_k^T u (block partials + atomics) ---
__global__ void __launch_bounds__(256) k_kv() {
    __shared__ float ph[32*64];
    __shared__ float us[32*128];
    int tid = threadIdx.x, b = blockIdx.y;
    int n0 = blockIdx.x*512;
    int tm = tid >> 4, tc = tid & 15;
    unsigned long long acc[4][4];
#pragma unroll
    for (int a = 0; a < 4; a++)
#pragma unroll
        for (int c = 0; c < 4; c++) acc[a][c] = 0ull;
    for (int ch = 0; ch < 16; ch++) {
        int nb = n0 + ch*32;
        int lr = tid >> 3, lf = tid & 7;
        int n = nb + lr;
        float4 z = make_float4(0.f, 0.f, 0.f, 0.f);
#pragma unroll
        for (int h2 = 0; h2 < 2; h2++) {
            int f = lf + h2*8;
            float4 v = z;
            if (n < NN) v = *(const float4*)&g_phik[(b*NN + n)*MM + f*4];
            *(float4*)&ph[lr*64 + f*4] = v;
        }
#pragma unroll
        for (int h2 = 0; h2 < 4; h2++) {
            int f = lf + h2*8;
            float4 v = z;
            if (n < NN) v = *(const float4*)&g_u[(b*NN + n)*CC + f*4];
            *(float4*)&us[lr*128 + f*4] = v;
        }
        __syncthreads();
#pragma unroll 8
        for (int r = 0; r < 32; r++) {
            float4 pk = *(float4*)&ph[r*64 + tm*4];
            float4 u0 = *(float4*)&us[r*128 + tc*8];
            float4 u1 = *(float4*)&us[r*128 + tc*8 + 4];
            unsigned long long up0, up1, up2, up3;
            PK2(up0, u0.x, u0.y); PK2(up1, u0.z, u0.w);
            PK2(up2, u1.x, u1.y); PK2(up3, u1.z, u1.w);
            unsigned long long a2;
            PK2(a2, pk.x, pk.x);
            FMA2(acc[0][0], a2, up0); FMA2(acc[0][1], a2, up1);
            FMA2(acc[0][2], a2, up2); FMA2(acc[0][3], a2, up3);
            PK2(a2, pk.y, pk.y);
            FMA2(acc[1][0], a2, up0); FMA2(acc[1][1], a2, up1);
            FMA2(acc[1][2], a2, up2); FMA2(acc[1][3], a2, up3);
            PK2(a2, pk.z, pk.z);
            FMA2(acc[2][0], a2, up0); FMA2(acc[2][1], a2, up1);
            FMA2(acc[2][2], a2, up2); FMA2(acc[2][3], a2, up3);
            PK2(a2, pk.w, pk.w);
            FMA2(acc[3][0], a2, up0); FMA2(acc[3][1], a2, up1);
            FMA2(acc[3][2], a2, up2); FMA2(acc[3][3], a2, up3);
        }
        __syncthreads();
    }
#pragma unroll
    for (int a = 0; a < 4; a++)
#pragma unroll
        for (int cp = 0; cp < 4; cp++) {
            float lo, hi;
            UPK2(lo, hi, acc[a][cp]);
            atomicAdd(&g_kv[b*MM*CC + (tm*4 + a)*CC + tc*8 + cp*2],     lo);
            atomicAdd(&g_kv[b*MM*CC + (tm*4 + a)*CC + tc*8 + cp*2 + 1], hi);
        }
}

// ---------------- per-layer: num/den + residual + LayerNorm --------------
__global__ void __launch_bounds__(256) k_attn(int li, const float* __restrict__ lng,
                                              const float* __restrict__ lnb) {
    __shared__ float skv[MM*CC];
    __shared__ float sphi[64*MM];
    __shared__ float sk[MM];
    __shared__ float sden[64];
    int tid = threadIdx.x, b = blockIdx.y;
    int r0 = blockIdx.x*64;
    for (int i = tid; i < MM*CC/4; i += 256)
        *(float4*)&skv[i*4] = *(const float4*)&g_kv[b*MM*CC + i*4];
    for (int i = tid; i < 64*MM/4; i += 256) {
        int row = (i*4) >> 6;
        float4 v = make_float4(0.f,0.f,0.f,0.f);
        if (r0 + row < NN) v = *(const float4*)&g_phiq[(b*NN + r0)*MM + i*4];
        *(float4*)&sphi[i*4] = v;
    }
    if (tid < MM) sk[tid] = g_ksum[b*MM + tid];
    __syncthreads();
    int tx = tid & 31, w = tid >> 5;
#pragma unroll
    for (int i = 0; i < 8; i++) {
        int row = w*8 + i;
        float v = sphi[row*MM + tx]*sk[tx] + sphi[row*MM + 32 + tx]*sk[32 + tx];
        for (int o = 16; o; o >>= 1) v += __shfl_xor_sync(0xffffffffu, v, o);
        if (tx == 0) sden[row] = v;
    }
    __syncthreads();
    unsigned long long acc[8][2];
#pragma unroll
    for (int i = 0; i < 8; i++) { acc[i][0] = 0ull; acc[i][1] = 0ull; }
    for (int m = 0; m < MM; m++) {
        float4 kv4 = *(float4*)&skv[m*CC + tx*4];
        unsigned long long k0, k1;
        PK2(k0, kv4.x, kv4.y); PK2(k1, kv4.z, kv4.w);
#pragma unroll
        for (int i = 0; i < 8; i++) {
            float a = sphi[(w*8 + i)*MM + m];
            unsigned long long a2; PK2(a2, a, a);
            FMA2(acc[i][0], a2, k0); FMA2(acc[i][1], a2, k1);
        }
    }
    float4 gam = *(const float4*)&lng[li*CC + tx*4];
    float4 bet = *(const float4*)&lnb[li*CC + tx*4];
#pragma unroll
    for (int i = 0; i < 8; i++) {
        int n = r0 + w*8 + i;
        if (n >= NN) continue;
        float x0, x1, x2, x3;
        UPK2(x0, x1, acc[i][0]); UPK2(x2, x3, acc[i][1]);
        float invd = 1.f / sden[w*8 + i];
        float4 h4 = *(const float4*)&g_h[(b*NN + n)*CC + tx*4];
        x0 = x0*invd + h4.x; x1 = x1*invd + h4.y;
        x2 = x2*invd + h4.z; x3 = x3*invd + h4.w;
        float s = x0 + x1 + x2 + x3;
        float q = x0*x0 + x1*x1 + x2*x2 + x3*x3;
        for (int o = 16; o; o >>= 1) {
            s += __shfl_xor_sync(0xffffffffu, s, o);
            q += __shfl_xor_sync(0xffffffffu, q, o);
        }
        float mu = s * (1.f/128.f);
        float var = q * (1.f/128.f) - mu*mu;
        float rs = rsqrtf(var + 1e-5f);
        float4 o4;
        o4.x = (x0 - mu)*rs*gam.x + bet.x;
        o4.y = (x1 - mu)*rs*gam.y + bet.y;
        o4.z = (x2 - mu)*rs*gam.z + bet.z;
        o4.w = (x3 - mu)*rs*gam.w + bet.w;
        *(float4*)&g_h[(b*NN + n)*CC + tx*4] = o4;
    }
}

// ---------------- K8: regression head ------------------------------------
__global__ void k_out(const float* __restrict__ reg_w, const float* __restrict__ reg_b,
                      float* __restrict__ out) {
    __shared__ float srw[PP*256];
    __shared__ float srb[PP];
    int tid = threadIdx.x;
    for (int i = tid; i < PP*256; i += 256) srw[i] = reg_w[i];
    if (tid < PP) srb[tid] = reg_b[tid];
    __syncthreads();
    int b = blockIdx.y;
    int n = blockIdx.x*256 + tid;
    if (n >= NN) return;
    float acc[PP];
#pragma unroll
    for (int p = 0; p < PP; p++) acc[p] = srb[p];
    int base = (b*NN + n)*CC;
#pragma unroll 4
    for (int c4 = 0; c4 < CC/4; c4++) {
        float4 s = *(const float4*)&g_skip[base + c4*4];
        float4 h = *(const float4*)&g_h[base + c4*4];
        float sv[4] = {s.x, s.y, s.z, s.w};
        float hv[4] = {h.x, h.y, h.z, h.w};
#pragma unroll
        for (int j = 0; j < 4; j++) {
            int c = c4*4 + j;
#pragma unroll
            for (int p = 0; p < PP; p++)
                acc[p] += sv[j]*srw[p*256 + c] + hv[j]*srw[p*256 + 128 + c];
        }
    }
#pragma unroll
    for (int p = 0; p < PP; p++) out[(b*PP + p)*NN + n] = acc[p];
}

// ---------------- launch --------------------------------------------------
extern "C" void kernel_launch(void* const* d_in, const int* in_sizes, int n_in,
                              void* d_out, int out_size) {
    const float* x        = (const float*)d_in[0];
    const float* xm       = (const float*)d_in[1];
    const float* node_emb = (const float*)d_in[2];
    const float* time_tab = (const float*)d_in[3];
    const float* week_tab = (const float*)d_in[4];
    const float* input_w  = (const float*)d_in[5];
    const float* input_b  = (const float*)d_in[6];
    const float* w1w      = (const float*)d_in[7];
    const float* w1b      = (const float*)d_in[8];
    const float* w2w      = (const float*)d_in[9];
    const float* w2b      = (const float*)d_in[10];
    const float* in_w     = (const float*)d_in[11];
    const float* in_b     = (const float*)d_in[12];
    const float* out_w    = (const float*)d_in[13];
    const float* out_b    = (const float*)d_in[14];
    const float* lng      = (const float*)d_in[15];
    const float* lnb      = (const float*)d_in[16];
    const float* reg_w    = (const float*)d_in[17];
    const float* reg_b    = (const float*)d_in[18];
    const float* proj     = (const float*)d_in[19];

    k_prep<<<1, 256>>>(xm, input_w, input_b, time_tab, week_tab, w1w, w1b, w2w, w2b);
    k_wcomb<<<384, 256>>>(in_w, out_w);
    k_embed<<<dim3(79, 8), 256>>>(x, input_w, node_emb, time_tab, week_tab);
    k_phi<<<dim3(313, 8), 256>>>(node_emb, w1w, w2w, proj);
    k_pkfin<<<dim3(40, 8), 256>>>();
    for (int li = 0; li < LL; li++) {
        k_zerokv<<<256, 256>>>();
        k_ugemm_mma<<<dim3(313, 8), 256>>>(li, in_b, out_b);
        k_kv<<<dim3(40, 8), 256>>>();
        k_attn<<<dim3(313, 8), 256>>>(li, lng, lnb);
    }
    k_out<<<dim3(79, 8), 256>>>(reg_w, reg_b, (float*)d_out);
}